// round 16
// baseline (speedup 1.0000x reference)
#include <cuda_runtime.h>
#include <math.h>

#define PA12(py,px) (((py)+1)*12 + (px) + 1)

__device__ float d_m0[8*64*64];
__device__ float d_m1[8*64*64];
__device__ float d_m2[8*64*64];
__device__ float d_mh0[8*32*64];
__device__ float d_mh1[8*32*64];
__device__ float d_r2[8*32*64];
__device__ float d_yo[8*32*64];
__device__ float d_wsum[64*9];
__device__ float d_etot[8*64*64];
__device__ float d_V[8*64*32*64];     // [b][i][o][p]
__device__ float d_w1p[2*32*64*12];   // [kres][r][ci][dy*4+dx]
__device__ float d_w1pB[2*32*3*64*4]; // [kres][r][dy][ci][4]
__device__ float d_w1pT[2*64*3*32*4]; // [kres][ci][dy][r][4]
__device__ float d_w1cp[64*64*12];
__device__ float d_xp[8*64*120];
__device__ float d_act[8*64*120];
__device__ float d_ys[8*64*64];
__device__ float d_h[8*32*64];
__device__ unsigned int g_bar;

__device__ __forceinline__ void ldrow12(const float* p, float* r) {
    float4 a = *(const float4*)p;
    float4 b = *(const float4*)(p + 4);
    float4 c = *(const float4*)(p + 8);
    r[0]=a.x; r[1]=a.y; r[2]=a.z; r[3]=a.w;
    r[4]=b.x; r[5]=b.y; r[6]=b.z; r[7]=b.w;
    r[8]=c.x; r[9]=c.y; r[10]=c.z; r[11]=c.w;
}
__device__ __forceinline__ void ldrow12cg(const float* p, float* r) {
    float4 a = __ldcg((const float4*)p);
    float4 b = __ldcg((const float4*)(p + 4));
    float4 c = __ldcg((const float4*)(p + 8));
    r[0]=a.x; r[1]=a.y; r[2]=a.z; r[3]=a.w;
    r[4]=b.x; r[5]=b.y; r[6]=b.z; r[7]=b.w;
    r[8]=c.x; r[9]=c.y; r[10]=c.z; r[11]=c.w;
}

__device__ __forceinline__ void gridbar(unsigned int target) {
    __syncthreads();
    if (threadIdx.x == 0) {
        __threadfence();
        atomicAdd(&g_bar, 1u);
        while (atomicAdd(&g_bar, 0u) < target) { }
    }
    __syncthreads();
}

// warp-per-pixel hopfield core. ps: smem patterns [512][32]; red: smem [8][32][33].
// yv[c] must hold src channel c at this warp's pixel. Returns q for lane's channel.
__device__ __forceinline__ float hop_core(const float* ps, float* red,
                                          const float* yv, int lane, int wid)
{
    float le[16], mx = -3.4e38f;
    #pragma unroll
    for (int k = 0; k < 16; k++) {
        const float* pr = ps + (lane + 32*k)*32;
        float a = 0.f;
        #pragma unroll
        for (int c = 0; c < 32; c++) a = fmaf(yv[c], pr[c], a);
        a *= 0.17677669529663688f;
        le[k] = a; mx = fmaxf(mx, a);
    }
    #pragma unroll
    for (int o = 16; o > 0; o >>= 1) mx = fmaxf(mx, __shfl_xor_sync(~0u, mx, o));
    float ssum = 0.f, accq[32];
    #pragma unroll
    for (int c = 0; c < 32; c++) accq[c] = 0.f;
    #pragma unroll
    for (int k = 0; k < 16; k++) {
        float pe = expf(le[k] - mx);
        ssum += pe;
        const float* pr = ps + (lane + 32*k)*32;
        #pragma unroll
        for (int c = 0; c < 32; c++) accq[c] = fmaf(pe, pr[c], accq[c]);
    }
    #pragma unroll
    for (int o = 16; o > 0; o >>= 1) ssum += __shfl_xor_sync(~0u, ssum, o);
    float* rw = red + wid*1056;
    #pragma unroll
    for (int c = 0; c < 32; c++) rw[lane*33 + c] = accq[c];
    __syncwarp();
    float colsum = 0.f;
    #pragma unroll
    for (int l = 0; l < 32; l++) colsum += rw[l*33 + lane];
    return colsum / ssum;
}

// ---- prep ----
__global__ void __launch_bounds__(256) prep_kernel(const float* x, const float* w1c,
                                                   const float* rw1a, const float* rw1b)
{
    int t = blockIdx.x*blockDim.x + threadIdx.x;
    if (t == 0) g_bar = 0u;
    if (t < 61440) {
        int b = t / 7680, j = t % 7680;
        int ci = j / 120, rr = j % 120;
        int py = rr/12 - 1, px = rr%12 - 1;
        float v = 0.f;
        if (py >= 0 && py < 8 && px >= 0 && px < 8)
            v = x[(b*64+ci)*64 + py*8 + px];
        d_xp[t] = v;
        d_act[t] = 0.f;
    }
    if (t < 49152) {
        int rem = t % 12, base = t / 12, dy = rem >> 2, dx = rem & 3;
        d_w1cp[t] = (dx < 3) ? w1c[base*9 + dy*3 + dx] : 0.f;
    }
    if (t < 24576) {
        {   int rem = t % 12, base = t / 12, dy = rem >> 2, dx = rem & 3;
            d_w1p[t]         = (dx < 3) ? rw1a[base*9 + dy*3 + dx] : 0.f;
            d_w1p[24576 + t] = (dx < 3) ? rw1b[base*9 + dy*3 + dx] : 0.f;
        }
        {   int dx = t & 3, rest = t >> 2;
            int ci = rest & 63, rd = rest >> 6;
            int dy = rd % 3, r = rd / 3;
            int src = (r*64 + ci)*9 + dy*3 + dx;
            d_w1pB[t]         = (dx < 3) ? rw1a[src] : 0.f;
            d_w1pB[24576 + t] = (dx < 3) ? rw1b[src] : 0.f;
        }
        {   int dx = t & 3, rest = t >> 2;
            int r = rest & 31, cd = rest >> 5;
            int dy = cd % 3, ci = cd / 3;
            int src = (r*64 + ci)*9 + dy*3 + dx;
            d_w1pT[t]         = (dx < 3) ? rw1a[src] : 0.f;
            d_w1pT[24576 + t] = (dx < 3) ? rw1b[src] : 0.f;
        }
    }
    if (t < 576) {
        int co = t/9, k = t%9; float s = 0.f;
        for (int ci = 0; ci < 64; ci++) s += w1c[(co*64+ci)*9 + k];
        d_wsum[t] = s;
    }
}

// ---- fwd2: layer-parallel forward + hopfield(r2). grid 64, 256 thr ----
__global__ void __launch_bounds__(256) fwd2_kernel(
                           const float* b1, const float* rw2a, const float* rw2b,
                           const float* w2c, const float* b2,
                           const float* __restrict__ pats)
{
    extern __shared__ float sm[];
    float* part = sm;           // 2048
    float* ps   = sm + 2048;    // 16384
    float* red  = ps + 16384;   // 8448
    int t = threadIdx.x;
    int b = blockIdx.x >> 3, chunk = blockIdx.x & 7;

    for (int i = t; i < 16384; i += 256) ps[i] = pats[i];

    // ---- phase A: conv1 3x3 64->64 ----
    {
        int quarter = t >> 6, co_l = (t >> 3) & 7, row = t & 7;
        int co = chunk*8 + co_l;
        float acc[8];
        #pragma unroll
        for (int q = 0; q < 8; q++) acc[q] = 0.f;
        for (int cc = 0; cc < 16; cc++) {
            int ci = quarter*16 + cc;
            const float* xb = d_xp + b*7680 + ci*120;
            #pragma unroll
            for (int dy = 0; dy < 3; dy++) {
                float xr[12]; ldrow12(xb + (row+dy)*12, xr);
                float4 w = __ldg((const float4*)(d_w1cp + (co*64+ci)*12 + dy*4));
                #pragma unroll
                for (int q = 0; q < 8; q++)
                    acc[q] += w.x*xr[q] + w.y*xr[q+1] + w.z*xr[q+2];
            }
        }
        #pragma unroll
        for (int q = 0; q < 8; q++) part[quarter*512 + co_l*64 + row*8 + q] = acc[q];
    }
    __syncthreads();
    for (int k = t; k < 512; k += 256) {
        int co2 = chunk*8 + (k >> 6), p = k & 63;
        float v = part[k] + part[512+k] + part[1024+k] + part[1536+k] + b1[co2];
        float m = v > 0.f ? 1.f : 0.f;
        d_ys[b*4096 + co2*64 + p] = v;
        d_m0[(b*64+co2)*64 + p] = m;
        d_act[b*7680 + co2*120 + PA12(p>>3, p&7)] = v*m;
    }
    gridbar(64);

    for (int kres = 0; kres < 2; kres++) {
        const float* rw2 = kres ? rw2b : rw2a;
        const float* w1p = d_w1p + kres*24576;
        float* dmh = kres ? d_mh1 : d_mh0;
        float* dm  = kres ? d_m2  : d_m1;

        { // phase B/D: res conv3x3 64->32
            int eighth = t >> 5, r_l = (t >> 3) & 3, row = t & 7;
            int r = chunk*4 + r_l;
            float acc[8];
            #pragma unroll
            for (int q = 0; q < 8; q++) acc[q] = 0.f;
            for (int cc = 0; cc < 8; cc++) {
                int ci = eighth*8 + cc;
                const float* xb = d_act + b*7680 + ci*120;
                #pragma unroll
                for (int dy = 0; dy < 3; dy++) {
                    float xr[12]; ldrow12cg(xb + (row+dy)*12, xr);
                    float4 w = __ldg((const float4*)(w1p + (r*64+ci)*12 + dy*4));
                    #pragma unroll
                    for (int q = 0; q < 8; q++)
                        acc[q] += w.x*xr[q] + w.y*xr[q+1] + w.z*xr[q+2];
                }
            }
            #pragma unroll
            for (int q = 0; q < 8; q++) part[eighth*256 + r_l*64 + row*8 + q] = acc[q];
        }
        __syncthreads();
        for (int k = t; k < 256; k += 256) {
            float v = 0.f;
            #pragma unroll
            for (int e = 0; e < 8; e++) v += part[e*256 + k];
            int r2 = chunk*4 + (k >> 6), p = k & 63;
            float m = v > 0.f ? 1.f : 0.f;
            dmh[(b*32+r2)*64 + p] = m;
            d_h[b*2048 + r2*64 + p] = v*m;
        }
        gridbar(kres ? 256 : 128);

        // phase C/E: res 1x1 32->64 + add + mask
        for (int k = chunk*512 + t; k < chunk*512 + 512; k += 256) {
            int ci = k >> 6, p = k & 63;
            float acc = d_ys[b*4096 + k];
            const float* hb = d_h + b*2048;
            #pragma unroll
            for (int rr = 0; rr < 8; rr++) {
                float4 w = __ldg((const float4*)(rw2 + ci*32 + rr*4));
                acc += w.x*__ldcg(hb + (rr*4+0)*64+p) + w.y*__ldcg(hb + (rr*4+1)*64+p)
                     + w.z*__ldcg(hb + (rr*4+2)*64+p) + w.w*__ldcg(hb + (rr*4+3)*64+p);
            }
            d_ys[b*4096 + k] = acc;
            float m = acc > 0.f ? 1.f : 0.f;
            dm[(b*64+ci)*64 + p] = m;
            d_act[b*7680 + ci*120 + PA12(p>>3, p&7)] = acc*m;
        }
        gridbar(kres ? 320 : 192);
    }

    // phase F: conv2 1x1 64->32 + bias -> d_yo
    {
        int o = chunk*4 + (t >> 6), p = t & 63;
        float acc = b2[o];
        int pa = PA12(p>>3, p&7);
        const float* ab = d_act + b*7680;
        #pragma unroll
        for (int cc = 0; cc < 16; cc++) {
            float4 w = __ldg((const float4*)(w2c + o*64 + cc*4));
            acc += w.x*__ldcg(ab + (cc*4+0)*120+pa) + w.y*__ldcg(ab + (cc*4+1)*120+pa)
                 + w.z*__ldcg(ab + (cc*4+2)*120+pa) + w.w*__ldcg(ab + (cc*4+3)*120+pa);
        }
        d_yo[b*2048 + o*64 + p] = acc;
    }
    gridbar(384);

    // phase G: hopfield mode 0: d_r2 = 2*(yo - q)
    {
        int lane = t & 31, wid = t >> 5;
        int p = chunk*8 + wid;
        const float* yb = d_yo + b*2048;
        float yv[32];
        #pragma unroll
        for (int c = 0; c < 32; c++) yv[c] = __ldcg(yb + c*64 + p);
        float q = hop_core(ps, red, yv, lane, wid);
        d_r2[b*2048 + lane*64 + p] = 2.f*(yv[lane] - q);
    }
}

// ---- seed: merged per-seed backward (z=0) + tangent (z=1). grid (64,8,2), 128 thr ----
__global__ void __launch_bounds__(128, 4) seed_kernel(
                           const float* x, const float* w1c,
                           const float* rw2a, const float* rw2b, const float* w2c)
{
    extern __shared__ float sm[];
    int t = threadIdx.x, b = blockIdx.y;

    if (blockIdx.z == 0) {
        float* gs  = sm;           // [64][120]
        float* as_ = gs + 7680;    // [32][120]
        int s = blockIdx.x;
        int sy = s >> 3;

        for (int i = t; i < 7680; i += 128) gs[i] = 0.f;
        for (int i = t; i < 3840; i += 128) as_[i] = 0.f;
        __syncthreads();

        if (t < 64) {
            float acc = 0.f;
            for (int o = 0; o < 32; o++) acc += d_r2[(b*32+o)*64 + s] * __ldg(w2c + o*64 + t);
            gs[t*120 + PA12(s>>3, s&7)] = acc * d_m2[(b*64+t)*64 + s];
        }
        __syncthreads();

        for (int kres = 1; kres >= 0; kres--) {
            const float* dmh = kres ? d_mh1 : d_mh0;
            const float* dm  = kres ? d_m1  : d_m0;
            const float* rw2 = kres ? rw2b : rw2a;
            const float* wB  = d_w1pB + kres*24576;
            {
                int row = t >> 4, rp = t & 15;
                int r0 = 2*rp, r1 = r0 + 1;
                int kk = kres ? 0 : 1;
                int lo = sy - kk < 0 ? 0 : sy - kk;
                int hi = sy + kk > 7 ? 7 : sy + kk;
                int prow = row & ~1;
                if (!(prow + 1 < lo || prow > hi)) {
                    float a0[8], a1[8];
                    #pragma unroll
                    for (int q = 0; q < 8; q++) { a0[q] = 0.f; a1[q] = 0.f; }
                    for (int ci = 0; ci < 64; ci++) {
                        float2 wv = __ldg((const float2*)(rw2 + ci*32 + rp*2));
                        float xr[12]; ldrow12(gs + ci*120 + (row+1)*12, xr);
                        #pragma unroll
                        for (int q = 0; q < 8; q++) {
                            a0[q] += wv.x*xr[q+1];
                            a1[q] += wv.y*xr[q+1];
                        }
                    }
                    const float* mh0 = dmh + (b*32+r0)*64 + row*8;
                    const float* mh1 = dmh + (b*32+r1)*64 + row*8;
                    float* ar0 = as_ + r0*120 + (row+1)*12 + 1;
                    float* ar1 = as_ + r1*120 + (row+1)*12 + 1;
                    #pragma unroll
                    for (int q = 0; q < 8; q++) { ar0[q] = a0[q]*mh0[q]; ar1[q] = a1[q]*mh1[q]; }
                }
            }
            __syncthreads();
            {
                int rp = t >> 5, cp = t & 31;
                int ci0 = 2*cp, ci1 = ci0 + 1, ro0 = 2*rp;
                int kk = kres ? 1 : 2;
                int lo = sy - kk < 0 ? 0 : sy - kk;
                int hi = sy + kk > 7 ? 7 : sy + kk;
                if (!(ro0 + 1 < lo || ro0 > hi)) {
                    float a00[8], a01[8], a10[8], a11[8];
                    #pragma unroll
                    for (int q = 0; q < 8; q++) { a00[q]=0.f; a01[q]=0.f; a10[q]=0.f; a11[q]=0.f; }
                    for (int r = 0; r < 32; r++) {
                        const float* base = as_ + r*120;
                        const float* wr = wB + r*768 + ci0*4;
                        float rA[12], rB[12];
                        ldrow12(base + (ro0+3)*12, rB);
                        ldrow12(base + (ro0+2)*12, rA);
                        float4 w0 = __ldg((const float4*)(wr + 0));
                        float4 w1 = __ldg((const float4*)(wr + 4));
                        #pragma unroll
                        for (int q = 0; q < 8; q++) {
                            a00[q] += w0.x*rA[q+2] + w0.y*rA[q+1] + w0.z*rA[q];
                            a01[q] += w0.x*rB[q+2] + w0.y*rB[q+1] + w0.z*rB[q];
                            a10[q] += w1.x*rA[q+2] + w1.y*rA[q+1] + w1.z*rA[q];
                            a11[q] += w1.x*rB[q+2] + w1.y*rB[q+1] + w1.z*rB[q];
                        }
                        ldrow12(base + (ro0+1)*12, rB);
                        w0 = __ldg((const float4*)(wr + 256));
                        w1 = __ldg((const float4*)(wr + 260));
                        #pragma unroll
                        for (int q = 0; q < 8; q++) {
                            a00[q] += w0.x*rB[q+2] + w0.y*rB[q+1] + w0.z*rB[q];
                            a01[q] += w0.x*rA[q+2] + w0.y*rA[q+1] + w0.z*rA[q];
                            a10[q] += w1.x*rB[q+2] + w1.y*rB[q+1] + w1.z*rB[q];
                            a11[q] += w1.x*rA[q+2] + w1.y*rA[q+1] + w1.z*rA[q];
                        }
                        ldrow12(base + ro0*12, rA);
                        w0 = __ldg((const float4*)(wr + 512));
                        w1 = __ldg((const float4*)(wr + 516));
                        #pragma unroll
                        for (int q = 0; q < 8; q++) {
                            a00[q] += w0.x*rA[q+2] + w0.y*rA[q+1] + w0.z*rA[q];
                            a01[q] += w0.x*rB[q+2] + w0.y*rB[q+1] + w0.z*rB[q];
                            a10[q] += w1.x*rA[q+2] + w1.y*rA[q+1] + w1.z*rA[q];
                            a11[q] += w1.x*rB[q+2] + w1.y*rB[q+1] + w1.z*rB[q];
                        }
                    }
                    int row0 = ro0, row1 = ro0 + 1;
                    const float* m00 = dm + (b*64+ci0)*64 + row0*8;
                    const float* m01 = dm + (b*64+ci0)*64 + row1*8;
                    const float* m10 = dm + (b*64+ci1)*64 + row0*8;
                    const float* m11 = dm + (b*64+ci1)*64 + row1*8;
                    float* g00 = gs + ci0*120 + (row0+1)*12 + 1;
                    float* g01 = gs + ci0*120 + (row1+1)*12 + 1;
                    float* g10 = gs + ci1*120 + (row0+1)*12 + 1;
                    float* g11 = gs + ci1*120 + (row1+1)*12 + 1;
                    #pragma unroll
                    for (int q = 0; q < 8; q++) {
                        g00[q] += a00[q]*m00[q];
                        g01[q] += a01[q]*m01[q];
                        g10[q] += a10[q]*m10[q];
                        g11[q] += a11[q]*m11[q];
                    }
                }
            }
            __syncthreads();
        }

        if (t < 64) {
            int qy = t >> 3, qx = t & 7;
            float acc = 0.f;
            for (int co = 0; co < 64; co++) {
                const float* gb = gs + co*120;
                const float* ws = d_wsum + co*9;
                #pragma unroll
                for (int dy = 0; dy < 3; dy++) {
                    const float* gr = gb + (qy-dy+2)*12 + 2;
                    acc += ws[dy*3+0]*gr[qx] + ws[dy*3+1]*gr[qx-1] + ws[dy*3+2]*gr[qx-2];
                }
            }
            d_etot[(b*64+s)*64 + t] = acc;
        }
    } else {
        float* ts  = sm;           // [64][64]
        float* tm  = ts + 4096;    // [64][120]
        float* tas = tm + 7680;    // [32][64]
        float* xv  = tas + 2048;   // 64
        int i = blockIdx.x;
        int iy = i >> 3, ix = i & 7;

        for (int k = t; k < 4096; k += 128) ts[k] = 0.f;
        for (int k = t; k < 7680; k += 128) tm[k] = 0.f;
        for (int k = t; k < 2048; k += 128) tas[k] = 0.f;
        if (t < 64) xv[t] = x[(b*64+t)*64 + i];
        __syncthreads();

        for (int task = t; task < 576; task += 128) {
            int co = task/9, d = task%9, dy = d/3, dx = d%3;
            int py = iy + 1 - dy, px = ix + 1 - dx;
            if (py >= 0 && py < 8 && px >= 0 && px < 8) {
                float acc = 0.f;
                for (int ci = 0; ci < 64; ci++) acc += __ldg(w1c + ((co*64+ci)*3+dy)*3+dx)*xv[ci];
                ts[co*64 + py*8 + px] = acc;
            }
        }
        __syncthreads();

        for (int kres = 0; kres < 2; kres++) {
            const float* dmh = kres ? d_mh1 : d_mh0;
            const float* dm  = kres ? d_m1  : d_m0;
            const float* rw2 = kres ? rw2b : rw2a;
            const float* wT  = d_w1pT + kres*24576;
            for (int k = t; k < 4096; k += 128) {
                int ci = k >> 6, p = k & 63;
                tm[ci*120 + PA12(p>>3, p&7)] = ts[k]*dm[(b*64+ci)*64 + p];
            }
            __syncthreads();
            {
                int rp = t >> 5, r = t & 31;
                int ro0 = 2*rp;
                int kk = kres ? 3 : 2;
                int lo = iy - kk < 0 ? 0 : iy - kk;
                int hi = iy + kk > 7 ? 7 : iy + kk;
                if (!(ro0 + 1 < lo || ro0 > hi)) {
                    float a0[8], a1[8];
                    #pragma unroll
                    for (int q = 0; q < 8; q++) { a0[q] = 0.f; a1[q] = 0.f; }
                    for (int ci = 0; ci < 64; ci++) {
                        const float* xb = tm + ci*120;
                        const float* wr = wT + ci*384 + r*4;
                        float rA[12], rB[12];
                        ldrow12(xb + (ro0+1)*12, rB);
                        ldrow12(xb + (ro0+0)*12, rA);
                        float4 w = __ldg((const float4*)(wr + 0));
                        #pragma unroll
                        for (int q = 0; q < 8; q++) {
                            a0[q] += w.x*rA[q] + w.y*rA[q+1] + w.z*rA[q+2];
                            a1[q] += w.x*rB[q] + w.y*rB[q+1] + w.z*rB[q+2];
                        }
                        ldrow12(xb + (ro0+2)*12, rA);
                        w = __ldg((const float4*)(wr + 128));
                        #pragma unroll
                        for (int q = 0; q < 8; q++) {
                            a0[q] += w.x*rB[q] + w.y*rB[q+1] + w.z*rB[q+2];
                            a1[q] += w.x*rA[q] + w.y*rA[q+1] + w.z*rA[q+2];
                        }
                        ldrow12(xb + (ro0+3)*12, rB);
                        w = __ldg((const float4*)(wr + 256));
                        #pragma unroll
                        for (int q = 0; q < 8; q++) {
                            a0[q] += w.x*rA[q] + w.y*rA[q+1] + w.z*rA[q+2];
                            a1[q] += w.x*rB[q] + w.y*rB[q+1] + w.z*rB[q+2];
                        }
                    }
                    const float* mh0 = dmh + (b*32+r)*64 + ro0*8;
                    const float* mh1 = dmh + (b*32+r)*64 + (ro0+1)*8;
                    #pragma unroll
                    for (int q = 0; q < 8; q++) {
                        tas[r*64 + ro0*8 + q]     = a0[q]*mh0[q];
                        tas[r*64 + (ro0+1)*8 + q] = a1[q]*mh1[q];
                    }
                }
            }
            __syncthreads();
            for (int k = t; k < 2048; k += 128) {
                int cp = k >> 6, p = k & 63;
                int ci0 = 2*cp, ci1 = ci0 + 1;
                float a0 = 0.f, a1 = 0.f;
                #pragma unroll
                for (int rr = 0; rr < 8; rr++) {
                    float4 w0 = __ldg((const float4*)(rw2 + ci0*32 + rr*4));
                    float4 w1 = __ldg((const float4*)(rw2 + ci1*32 + rr*4));
                    float t0 = tas[(rr*4+0)*64+p], t1 = tas[(rr*4+1)*64+p];
                    float t2 = tas[(rr*4+2)*64+p], t3 = tas[(rr*4+3)*64+p];
                    a0 += w0.x*t0 + w0.y*t1 + w0.z*t2 + w0.w*t3;
                    a1 += w1.x*t0 + w1.y*t1 + w1.z*t2 + w1.w*t3;
                }
                ts[ci0*64 + p] += a0;
                ts[ci1*64 + p] += a1;
            }
            __syncthreads();
        }

        for (int k = t; k < 4096; k += 128) {
            int ci = k >> 6, p = k & 63;
            tm[k] = ts[k]*d_m2[(b*64+ci)*64 + p];
        }
        __syncthreads();
        for (int k = t; k < 1024; k += 128) {
            int op = k >> 6, p = k & 63;
            int o0 = 2*op, o1 = o0 + 1;
            float a0 = 0.f, a1 = 0.f;
            #pragma unroll
            for (int cc = 0; cc < 16; cc++) {
                float4 w0 = __ldg((const float4*)(w2c + o0*64 + cc*4));
                float4 w1 = __ldg((const float4*)(w2c + o1*64 + cc*4));
                float t0 = tm[(cc*4+0)*64+p], t1 = tm[(cc*4+1)*64+p];
                float t2 = tm[(cc*4+2)*64+p], t3 = tm[(cc*4+3)*64+p];
                a0 += w0.x*t0 + w0.y*t1 + w0.z*t2 + w0.w*t3;
                a1 += w1.x*t0 + w1.y*t1 + w1.z*t2 + w1.w*t3;
            }
            d_V[((b*64+i)*32 + o0)*64 + p] = a0;
            d_V[((b*64+i)*32 + o1)*64 + p] = a1;
        }
    }
}

// ---- final: argmin + gather + scatter + hopfield(out). grid 64, 256 thr ----
__global__ void __launch_bounds__(256) final_kernel(const float* __restrict__ pats,
                                                    float* __restrict__ out)
{
    extern __shared__ float sm[];
    float* ps  = sm;            // 16384
    float* red = ps + 16384;    // 8448
    float* Us  = red + 8448;    // 2048
    float* ym  = Us + 2048;     // 2048
    int*   ix  = (int*)(ym + 2048);  // 64
    int t = threadIdx.x;
    int b = blockIdx.x >> 3, chunk = blockIdx.x & 7;

    for (int i = t; i < 16384; i += 256) ps[i] = pats[i];
    if (t < 64) { // argmin (redundant per sample's 8 CTAs; cheap)
        float best = d_etot[(b*64+0)*64 + t]; int bi = 0;
        for (int s = 1; s < 64; s++) {
            float v = d_etot[(b*64+s)*64 + t];
            if (v < best) { best = v; bi = s; }
        }
        ix[t] = bi;
    }
    __syncthreads();
    for (int k = t; k < 2048; k += 256) {
        int i = k >> 5, o = k & 31;
        Us[k] = d_V[((b*64+i)*32 + o)*64 + ix[i]];
    }
    __syncthreads();
    for (int k = t; k < 2048; k += 256) {
        int o = k >> 6, m = k & 63;
        float acc = 0.f;
        for (int ii = 0; ii < 64; ii++)
            acc += (ix[ii] == m) ? Us[ii*32 + o] : 0.f;
        ym[o*64 + m] = acc;
    }
    __syncthreads();
    {
        int lane = t & 31, wid = t >> 5;
        int p = chunk*8 + wid;
        float yv[32];
        #pragma unroll
        for (int c = 0; c < 32; c++) yv[c] = ym[c*64 + p];
        float q = hop_core(ps, red, yv, lane, wid);
        out[b*2048 + lane*64 + p] = q;
    }
}

extern "C" void kernel_launch(void* const* d_in, const int* in_sizes, int n_in,
                              void* d_out, int out_size)
{
    const float* x    = (const float*)d_in[0];
    const float* w1c  = (const float*)d_in[1];
    const float* b1   = (const float*)d_in[2];
    const float* rw1a = (const float*)d_in[3];
    const float* rw2a = (const float*)d_in[4];
    const float* rw1b = (const float*)d_in[5];
    const float* rw2b = (const float*)d_in[6];
    const float* w2c  = (const float*)d_in[7];
    const float* b2   = (const float*)d_in[8];
    const float* pats = (const float*)d_in[9];
    float* out = (float*)d_out;

    const int SEED = 13888*4;                      // 55.5 KB -> 4 CTAs/SM
    const int FWD2 = (2048 + 16384 + 8448)*4;      // 107.5 KB
    const int FIN  = (16384 + 8448 + 2048 + 2048 + 64)*4;  // 116 KB
    cudaFuncSetAttribute(seed_kernel,  cudaFuncAttributeMaxDynamicSharedMemorySize, SEED);
    cudaFuncSetAttribute(fwd2_kernel,  cudaFuncAttributeMaxDynamicSharedMemorySize, FWD2);
    cudaFuncSetAttribute(final_kernel, cudaFuncAttributeMaxDynamicSharedMemorySize, FIN);

    prep_kernel<<<240, 256>>>(x, w1c, rw1a, rw1b);
    fwd2_kernel<<<64, 256, FWD2>>>(b1, rw2a, rw2b, w2c, b2, pats);
    seed_kernel<<<dim3(64,8,2), 128, SEED>>>(x, w1c, rw2a, rw2b, w2c);
    final_kernel<<<64, 256, FIN>>>(pats, out);
}

// round 17
// speedup vs baseline: 1.1334x; 1.1334x over previous
#include <cuda_runtime.h>
#include <math.h>

#define PA12(py,px) (((py)+1)*12 + (px) + 1)

__device__ float d_m0[8*64*64];
__device__ float d_m1[8*64*64];
__device__ float d_m2[8*64*64];
__device__ float d_mh0[8*32*64];
__device__ float d_mh1[8*32*64];
__device__ float d_r2[8*32*64];
__device__ float d_yo[8*32*64];
__device__ float d_wsum[64*9];
__device__ float d_etot[8*64*64];
__device__ float d_V[8*64*32*64];     // [b][i][o][p]
__device__ float d_w1p[2*32*64*12];   // [kres][r][ci][dy*4+dx]
__device__ float d_w1pB[2*32*3*64*4]; // [kres][r][dy][ci][4]
__device__ float d_w1pT[2*64*3*32*4]; // [kres][ci][dy][r][4]
__device__ float d_w1cp[64*64*12];
__device__ float d_xp[8*64*120];
__device__ float d_act[8*64*120];
__device__ float d_ys[8*64*64];
__device__ float d_h[8*32*64];
__device__ unsigned int g_bar;

__device__ __forceinline__ void ldrow12(const float* p, float* r) {
    float4 a = *(const float4*)p;
    float4 b = *(const float4*)(p + 4);
    float4 c = *(const float4*)(p + 8);
    r[0]=a.x; r[1]=a.y; r[2]=a.z; r[3]=a.w;
    r[4]=b.x; r[5]=b.y; r[6]=b.z; r[7]=b.w;
    r[8]=c.x; r[9]=c.y; r[10]=c.z; r[11]=c.w;
}
__device__ __forceinline__ void ldrow12cg(const float* p, float* r) {
    float4 a = __ldcg((const float4*)p);
    float4 b = __ldcg((const float4*)(p + 4));
    float4 c = __ldcg((const float4*)(p + 8));
    r[0]=a.x; r[1]=a.y; r[2]=a.z; r[3]=a.w;
    r[4]=b.x; r[5]=b.y; r[6]=b.z; r[7]=b.w;
    r[8]=c.x; r[9]=c.y; r[10]=c.z; r[11]=c.w;
}

__device__ __forceinline__ void gridbar(unsigned int target) {
    __syncthreads();
    if (threadIdx.x == 0) {
        __threadfence();
        atomicAdd(&g_bar, 1u);
        while (atomicAdd(&g_bar, 0u) < target) { }
    }
    __syncthreads();
}

// warp-per-pixel hopfield core. ps: smem patterns [512][33] (PADDED, conflict-free);
// red: smem [8][32][33]. yv[c] = src channel c at this warp's pixel.
__device__ __forceinline__ float hop_core(const float* ps, float* red,
                                          const float* yv, int lane, int wid)
{
    float le[16], mx = -3.4e38f;
    #pragma unroll
    for (int k = 0; k < 16; k++) {
        const float* pr = ps + (lane + 32*k)*33;
        float a = 0.f;
        #pragma unroll
        for (int c = 0; c < 32; c++) a = fmaf(yv[c], pr[c], a);
        a *= 0.17677669529663688f;
        le[k] = a; mx = fmaxf(mx, a);
    }
    #pragma unroll
    for (int o = 16; o > 0; o >>= 1) mx = fmaxf(mx, __shfl_xor_sync(~0u, mx, o));
    float ssum = 0.f, accq[32];
    #pragma unroll
    for (int c = 0; c < 32; c++) accq[c] = 0.f;
    #pragma unroll
    for (int k = 0; k < 16; k++) {
        float pe = expf(le[k] - mx);
        ssum += pe;
        const float* pr = ps + (lane + 32*k)*33;
        #pragma unroll
        for (int c = 0; c < 32; c++) accq[c] = fmaf(pe, pr[c], accq[c]);
    }
    #pragma unroll
    for (int o = 16; o > 0; o >>= 1) ssum += __shfl_xor_sync(~0u, ssum, o);
    float* rw = red + wid*1056;
    #pragma unroll
    for (int c = 0; c < 32; c++) rw[lane*33 + c] = accq[c];
    __syncwarp();
    float colsum = 0.f;
    #pragma unroll
    for (int l = 0; l < 32; l++) colsum += rw[l*33 + lane];
    return colsum / ssum;
}

// load patterns into padded smem [512][33]
__device__ __forceinline__ void load_ps(float* ps, const float* pats, int t, int nthr) {
    for (int i = t; i < 16384; i += nthr)
        ps[(i >> 5)*33 + (i & 31)] = pats[i];
}

// ---- prep ----
__global__ void __launch_bounds__(256) prep_kernel(const float* x, const float* w1c,
                                                   const float* rw1a, const float* rw1b)
{
    int t = blockIdx.x*blockDim.x + threadIdx.x;
    if (t == 0) g_bar = 0u;
    if (t < 61440) {
        int b = t / 7680, j = t % 7680;
        int ci = j / 120, rr = j % 120;
        int py = rr/12 - 1, px = rr%12 - 1;
        float v = 0.f;
        if (py >= 0 && py < 8 && px >= 0 && px < 8)
            v = x[(b*64+ci)*64 + py*8 + px];
        d_xp[t] = v;
        d_act[t] = 0.f;
    }
    if (t < 49152) {
        int rem = t % 12, base = t / 12, dy = rem >> 2, dx = rem & 3;
        d_w1cp[t] = (dx < 3) ? w1c[base*9 + dy*3 + dx] : 0.f;
    }
    if (t < 24576) {
        {   int rem = t % 12, base = t / 12, dy = rem >> 2, dx = rem & 3;
            d_w1p[t]         = (dx < 3) ? rw1a[base*9 + dy*3 + dx] : 0.f;
            d_w1p[24576 + t] = (dx < 3) ? rw1b[base*9 + dy*3 + dx] : 0.f;
        }
        {   int dx = t & 3, rest = t >> 2;
            int ci = rest & 63, rd = rest >> 6;
            int dy = rd % 3, r = rd / 3;
            int src = (r*64 + ci)*9 + dy*3 + dx;
            d_w1pB[t]         = (dx < 3) ? rw1a[src] : 0.f;
            d_w1pB[24576 + t] = (dx < 3) ? rw1b[src] : 0.f;
        }
        {   int dx = t & 3, rest = t >> 2;
            int r = rest & 31, cd = rest >> 5;
            int dy = cd % 3, ci = cd / 3;
            int src = (r*64 + ci)*9 + dy*3 + dx;
            d_w1pT[t]         = (dx < 3) ? rw1a[src] : 0.f;
            d_w1pT[24576 + t] = (dx < 3) ? rw1b[src] : 0.f;
        }
    }
    if (t < 576) {
        int co = t/9, k = t%9; float s = 0.f;
        for (int ci = 0; ci < 64; ci++) s += w1c[(co*64+ci)*9 + k];
        d_wsum[t] = s;
    }
}

// ---- fwd2: layer-parallel forward + hopfield(r2). grid 64, 256 thr ----
__global__ void __launch_bounds__(256) fwd2_kernel(
                           const float* b1, const float* rw2a, const float* rw2b,
                           const float* w2c, const float* b2,
                           const float* __restrict__ pats)
{
    extern __shared__ float sm[];
    float* part = sm;           // 2048
    float* ps   = sm + 2048;    // 512*33 = 16896
    float* red  = ps + 16896;   // 8448
    int t = threadIdx.x;
    int b = blockIdx.x >> 3, chunk = blockIdx.x & 7;

    load_ps(ps, pats, t, 256);

    // ---- phase A: conv1 3x3 64->64 ----
    {
        int quarter = t >> 6, co_l = (t >> 3) & 7, row = t & 7;
        int co = chunk*8 + co_l;
        float acc[8];
        #pragma unroll
        for (int q = 0; q < 8; q++) acc[q] = 0.f;
        for (int cc = 0; cc < 16; cc++) {
            int ci = quarter*16 + cc;
            const float* xb = d_xp + b*7680 + ci*120;
            #pragma unroll
            for (int dy = 0; dy < 3; dy++) {
                float xr[12]; ldrow12(xb + (row+dy)*12, xr);
                float4 w = __ldg((const float4*)(d_w1cp + (co*64+ci)*12 + dy*4));
                #pragma unroll
                for (int q = 0; q < 8; q++)
                    acc[q] += w.x*xr[q] + w.y*xr[q+1] + w.z*xr[q+2];
            }
        }
        #pragma unroll
        for (int q = 0; q < 8; q++) part[quarter*512 + co_l*64 + row*8 + q] = acc[q];
    }
    __syncthreads();
    for (int k = t; k < 512; k += 256) {
        int co2 = chunk*8 + (k >> 6), p = k & 63;
        float v = part[k] + part[512+k] + part[1024+k] + part[1536+k] + b1[co2];
        float m = v > 0.f ? 1.f : 0.f;
        d_ys[b*4096 + co2*64 + p] = v;
        d_m0[(b*64+co2)*64 + p] = m;
        d_act[b*7680 + co2*120 + PA12(p>>3, p&7)] = v*m;
    }
    gridbar(64);

    for (int kres = 0; kres < 2; kres++) {
        const float* rw2 = kres ? rw2b : rw2a;
        const float* w1p = d_w1p + kres*24576;
        float* dmh = kres ? d_mh1 : d_mh0;
        float* dm  = kres ? d_m2  : d_m1;

        { // phase B/D: res conv3x3 64->32
            int eighth = t >> 5, r_l = (t >> 3) & 3, row = t & 7;
            int r = chunk*4 + r_l;
            float acc[8];
            #pragma unroll
            for (int q = 0; q < 8; q++) acc[q] = 0.f;
            for (int cc = 0; cc < 8; cc++) {
                int ci = eighth*8 + cc;
                const float* xb = d_act + b*7680 + ci*120;
                #pragma unroll
                for (int dy = 0; dy < 3; dy++) {
                    float xr[12]; ldrow12cg(xb + (row+dy)*12, xr);
                    float4 w = __ldg((const float4*)(w1p + (r*64+ci)*12 + dy*4));
                    #pragma unroll
                    for (int q = 0; q < 8; q++)
                        acc[q] += w.x*xr[q] + w.y*xr[q+1] + w.z*xr[q+2];
                }
            }
            #pragma unroll
            for (int q = 0; q < 8; q++) part[eighth*256 + r_l*64 + row*8 + q] = acc[q];
        }
        __syncthreads();
        for (int k = t; k < 256; k += 256) {
            float v = 0.f;
            #pragma unroll
            for (int e = 0; e < 8; e++) v += part[e*256 + k];
            int r2 = chunk*4 + (k >> 6), p = k & 63;
            float m = v > 0.f ? 1.f : 0.f;
            dmh[(b*32+r2)*64 + p] = m;
            d_h[b*2048 + r2*64 + p] = v*m;
        }
        gridbar(kres ? 256 : 128);

        // phase C/E: res 1x1 32->64 + add + mask
        for (int k = chunk*512 + t; k < chunk*512 + 512; k += 256) {
            int ci = k >> 6, p = k & 63;
            float acc = d_ys[b*4096 + k];
            const float* hb = d_h + b*2048;
            #pragma unroll
            for (int rr = 0; rr < 8; rr++) {
                float4 w = __ldg((const float4*)(rw2 + ci*32 + rr*4));
                acc += w.x*__ldcg(hb + (rr*4+0)*64+p) + w.y*__ldcg(hb + (rr*4+1)*64+p)
                     + w.z*__ldcg(hb + (rr*4+2)*64+p) + w.w*__ldcg(hb + (rr*4+3)*64+p);
            }
            d_ys[b*4096 + k] = acc;
            float m = acc > 0.f ? 1.f : 0.f;
            dm[(b*64+ci)*64 + p] = m;
            d_act[b*7680 + ci*120 + PA12(p>>3, p&7)] = acc*m;
        }
        gridbar(kres ? 320 : 192);
    }

    // phase F: conv2 1x1 64->32 + bias -> d_yo
    {
        int o = chunk*4 + (t >> 6), p = t & 63;
        float acc = b2[o];
        int pa = PA12(p>>3, p&7);
        const float* ab = d_act + b*7680;
        #pragma unroll
        for (int cc = 0; cc < 16; cc++) {
            float4 w = __ldg((const float4*)(w2c + o*64 + cc*4));
            acc += w.x*__ldcg(ab + (cc*4+0)*120+pa) + w.y*__ldcg(ab + (cc*4+1)*120+pa)
                 + w.z*__ldcg(ab + (cc*4+2)*120+pa) + w.w*__ldcg(ab + (cc*4+3)*120+pa);
        }
        d_yo[b*2048 + o*64 + p] = acc;
    }
    gridbar(384);

    // phase G: hopfield mode 0: d_r2 = 2*(yo - q)
    {
        int lane = t & 31, wid = t >> 5;
        int p = chunk*8 + wid;
        const float* yb = d_yo + b*2048;
        float yv[32];
        #pragma unroll
        for (int c = 0; c < 32; c++) yv[c] = __ldcg(yb + c*64 + p);
        float q = hop_core(ps, red, yv, lane, wid);
        d_r2[b*2048 + lane*64 + p] = 2.f*(yv[lane] - q);
    }
}

// ---- seed: merged per-seed backward (z=0) + tangent (z=1). grid (64,8,2), 128 thr ----
__global__ void __launch_bounds__(128, 4) seed_kernel(
                           const float* x, const float* w1c,
                           const float* rw2a, const float* rw2b, const float* w2c)
{
    extern __shared__ float sm[];
    int t = threadIdx.x, b = blockIdx.y;

    if (blockIdx.z == 0) {
        float* gs  = sm;           // [64][120]
        float* as_ = gs + 7680;    // [32][120]
        int s = blockIdx.x;
        int sy = s >> 3;

        for (int i = t; i < 7680; i += 128) gs[i] = 0.f;
        for (int i = t; i < 3840; i += 128) as_[i] = 0.f;
        __syncthreads();

        if (t < 64) {
            float acc = 0.f;
            for (int o = 0; o < 32; o++) acc += d_r2[(b*32+o)*64 + s] * __ldg(w2c + o*64 + t);
            gs[t*120 + PA12(s>>3, s&7)] = acc * d_m2[(b*64+t)*64 + s];
        }
        __syncthreads();

        for (int kres = 1; kres >= 0; kres--) {
            const float* dmh = kres ? d_mh1 : d_mh0;
            const float* dm  = kres ? d_m1  : d_m0;
            const float* rw2 = kres ? rw2b : rw2a;
            const float* wB  = d_w1pB + kres*24576;
            {
                int row = t >> 4, rp = t & 15;
                int r0 = 2*rp, r1 = r0 + 1;
                int kk = kres ? 0 : 1;
                int lo = sy - kk < 0 ? 0 : sy - kk;
                int hi = sy + kk > 7 ? 7 : sy + kk;
                int prow = row & ~1;
                if (!(prow + 1 < lo || prow > hi)) {
                    float a0[8], a1[8];
                    #pragma unroll
                    for (int q = 0; q < 8; q++) { a0[q] = 0.f; a1[q] = 0.f; }
                    for (int ci = 0; ci < 64; ci++) {
                        float2 wv = __ldg((const float2*)(rw2 + ci*32 + rp*2));
                        float xr[12]; ldrow12(gs + ci*120 + (row+1)*12, xr);
                        #pragma unroll
                        for (int q = 0; q < 8; q++) {
                            a0[q] += wv.x*xr[q+1];
                            a1[q] += wv.y*xr[q+1];
                        }
                    }
                    const float* mh0 = dmh + (b*32+r0)*64 + row*8;
                    const float* mh1 = dmh + (b*32+r1)*64 + row*8;
                    float* ar0 = as_ + r0*120 + (row+1)*12 + 1;
                    float* ar1 = as_ + r1*120 + (row+1)*12 + 1;
                    #pragma unroll
                    for (int q = 0; q < 8; q++) { ar0[q] = a0[q]*mh0[q]; ar1[q] = a1[q]*mh1[q]; }
                }
            }
            __syncthreads();
            {
                int rp = t >> 5, cp = t & 31;
                int ci0 = 2*cp, ci1 = ci0 + 1, ro0 = 2*rp;
                int kk = kres ? 1 : 2;
                int lo = sy - kk < 0 ? 0 : sy - kk;
                int hi = sy + kk > 7 ? 7 : sy + kk;
                if (!(ro0 + 1 < lo || ro0 > hi)) {
                    float a00[8], a01[8], a10[8], a11[8];
                    #pragma unroll
                    for (int q = 0; q < 8; q++) { a00[q]=0.f; a01[q]=0.f; a10[q]=0.f; a11[q]=0.f; }
                    for (int r = 0; r < 32; r++) {
                        const float* base = as_ + r*120;
                        const float* wr = wB + r*768 + ci0*4;
                        float rA[12], rB[12];
                        ldrow12(base + (ro0+3)*12, rB);
                        ldrow12(base + (ro0+2)*12, rA);
                        float4 w0 = __ldg((const float4*)(wr + 0));
                        float4 w1 = __ldg((const float4*)(wr + 4));
                        #pragma unroll
                        for (int q = 0; q < 8; q++) {
                            a00[q] += w0.x*rA[q+2] + w0.y*rA[q+1] + w0.z*rA[q];
                            a01[q] += w0.x*rB[q+2] + w0.y*rB[q+1] + w0.z*rB[q];
                            a10[q] += w1.x*rA[q+2] + w1.y*rA[q+1] + w1.z*rA[q];
                            a11[q] += w1.x*rB[q+2] + w1.y*rB[q+1] + w1.z*rB[q];
                        }
                        ldrow12(base + (ro0+1)*12, rB);
                        w0 = __ldg((const float4*)(wr + 256));
                        w1 = __ldg((const float4*)(wr + 260));
                        #pragma unroll
                        for (int q = 0; q < 8; q++) {
                            a00[q] += w0.x*rB[q+2] + w0.y*rB[q+1] + w0.z*rB[q];
                            a01[q] += w0.x*rA[q+2] + w0.y*rA[q+1] + w0.z*rA[q];
                            a10[q] += w1.x*rB[q+2] + w1.y*rB[q+1] + w1.z*rB[q];
                            a11[q] += w1.x*rA[q+2] + w1.y*rA[q+1] + w1.z*rA[q];
                        }
                        ldrow12(base + ro0*12, rA);
                        w0 = __ldg((const float4*)(wr + 512));
                        w1 = __ldg((const float4*)(wr + 516));
                        #pragma unroll
                        for (int q = 0; q < 8; q++) {
                            a00[q] += w0.x*rA[q+2] + w0.y*rA[q+1] + w0.z*rA[q];
                            a01[q] += w0.x*rB[q+2] + w0.y*rB[q+1] + w0.z*rB[q];
                            a10[q] += w1.x*rA[q+2] + w1.y*rA[q+1] + w1.z*rA[q];
                            a11[q] += w1.x*rB[q+2] + w1.y*rB[q+1] + w1.z*rB[q];
                        }
                    }
                    int row0 = ro0, row1 = ro0 + 1;
                    const float* m00 = dm + (b*64+ci0)*64 + row0*8;
                    const float* m01 = dm + (b*64+ci0)*64 + row1*8;
                    const float* m10 = dm + (b*64+ci1)*64 + row0*8;
                    const float* m11 = dm + (b*64+ci1)*64 + row1*8;
                    float* g00 = gs + ci0*120 + (row0+1)*12 + 1;
                    float* g01 = gs + ci0*120 + (row1+1)*12 + 1;
                    float* g10 = gs + ci1*120 + (row0+1)*12 + 1;
                    float* g11 = gs + ci1*120 + (row1+1)*12 + 1;
                    #pragma unroll
                    for (int q = 0; q < 8; q++) {
                        g00[q] += a00[q]*m00[q];
                        g01[q] += a01[q]*m01[q];
                        g10[q] += a10[q]*m10[q];
                        g11[q] += a11[q]*m11[q];
                    }
                }
            }
            __syncthreads();
        }

        if (t < 64) {
            int qy = t >> 3, qx = t & 7;
            float acc = 0.f;
            for (int co = 0; co < 64; co++) {
                const float* gb = gs + co*120;
                const float* ws = d_wsum + co*9;
                #pragma unroll
                for (int dy = 0; dy < 3; dy++) {
                    const float* gr = gb + (qy-dy+2)*12 + 2;
                    acc += ws[dy*3+0]*gr[qx] + ws[dy*3+1]*gr[qx-1] + ws[dy*3+2]*gr[qx-2];
                }
            }
            d_etot[(b*64+s)*64 + t] = acc;
        }
    } else {
        float* ts  = sm;           // [64][64]
        float* tm  = ts + 4096;    // [64][120]
        float* tas = tm + 7680;    // [32][64]
        float* xv  = tas + 2048;   // 64
        int i = blockIdx.x;
        int iy = i >> 3, ix = i & 7;

        for (int k = t; k < 4096; k += 128) ts[k] = 0.f;
        for (int k = t; k < 7680; k += 128) tm[k] = 0.f;
        for (int k = t; k < 2048; k += 128) tas[k] = 0.f;
        if (t < 64) xv[t] = x[(b*64+t)*64 + i];
        __syncthreads();

        for (int task = t; task < 576; task += 128) {
            int co = task/9, d = task%9, dy = d/3, dx = d%3;
            int py = iy + 1 - dy, px = ix + 1 - dx;
            if (py >= 0 && py < 8 && px >= 0 && px < 8) {
                float acc = 0.f;
                for (int ci = 0; ci < 64; ci++) acc += __ldg(w1c + ((co*64+ci)*3+dy)*3+dx)*xv[ci];
                ts[co*64 + py*8 + px] = acc;
            }
        }
        __syncthreads();

        for (int kres = 0; kres < 2; kres++) {
            const float* dmh = kres ? d_mh1 : d_mh0;
            const float* dm  = kres ? d_m1  : d_m0;
            const float* rw2 = kres ? rw2b : rw2a;
            const float* wT  = d_w1pT + kres*24576;
            for (int k = t; k < 4096; k += 128) {
                int ci = k >> 6, p = k & 63;
                tm[ci*120 + PA12(p>>3, p&7)] = ts[k]*dm[(b*64+ci)*64 + p];
            }
            __syncthreads();
            {
                int rp = t >> 5, r = t & 31;
                int ro0 = 2*rp;
                int kk = kres ? 3 : 2;
                int lo = iy - kk < 0 ? 0 : iy - kk;
                int hi = iy + kk > 7 ? 7 : iy + kk;
                if (!(ro0 + 1 < lo || ro0 > hi)) {
                    float a0[8], a1[8];
                    #pragma unroll
                    for (int q = 0; q < 8; q++) { a0[q] = 0.f; a1[q] = 0.f; }
                    for (int ci = 0; ci < 64; ci++) {
                        const float* xb = tm + ci*120;
                        const float* wr = wT + ci*384 + r*4;
                        float rA[12], rB[12];
                        ldrow12(xb + (ro0+1)*12, rB);
                        ldrow12(xb + (ro0+0)*12, rA);
                        float4 w = __ldg((const float4*)(wr + 0));
                        #pragma unroll
                        for (int q = 0; q < 8; q++) {
                            a0[q] += w.x*rA[q] + w.y*rA[q+1] + w.z*rA[q+2];
                            a1[q] += w.x*rB[q] + w.y*rB[q+1] + w.z*rB[q+2];
                        }
                        ldrow12(xb + (ro0+2)*12, rA);
                        w = __ldg((const float4*)(wr + 128));
                        #pragma unroll
                        for (int q = 0; q < 8; q++) {
                            a0[q] += w.x*rB[q] + w.y*rB[q+1] + w.z*rB[q+2];
                            a1[q] += w.x*rA[q] + w.y*rA[q+1] + w.z*rA[q+2];
                        }
                        ldrow12(xb + (ro0+3)*12, rB);
                        w = __ldg((const float4*)(wr + 256));
                        #pragma unroll
                        for (int q = 0; q < 8; q++) {
                            a0[q] += w.x*rA[q] + w.y*rA[q+1] + w.z*rA[q+2];
                            a1[q] += w.x*rB[q] + w.y*rB[q+1] + w.z*rB[q+2];
                        }
                    }
                    const float* mh0 = dmh + (b*32+r)*64 + ro0*8;
                    const float* mh1 = dmh + (b*32+r)*64 + (ro0+1)*8;
                    #pragma unroll
                    for (int q = 0; q < 8; q++) {
                        tas[r*64 + ro0*8 + q]     = a0[q]*mh0[q];
                        tas[r*64 + (ro0+1)*8 + q] = a1[q]*mh1[q];
                    }
                }
            }
            __syncthreads();
            for (int k = t; k < 2048; k += 128) {
                int cp = k >> 6, p = k & 63;
                int ci0 = 2*cp, ci1 = ci0 + 1;
                float a0 = 0.f, a1 = 0.f;
                #pragma unroll
                for (int rr = 0; rr < 8; rr++) {
                    float4 w0 = __ldg((const float4*)(rw2 + ci0*32 + rr*4));
                    float4 w1 = __ldg((const float4*)(rw2 + ci1*32 + rr*4));
                    float t0 = tas[(rr*4+0)*64+p], t1 = tas[(rr*4+1)*64+p];
                    float t2 = tas[(rr*4+2)*64+p], t3 = tas[(rr*4+3)*64+p];
                    a0 += w0.x*t0 + w0.y*t1 + w0.z*t2 + w0.w*t3;
                    a1 += w1.x*t0 + w1.y*t1 + w1.z*t2 + w1.w*t3;
                }
                ts[ci0*64 + p] += a0;
                ts[ci1*64 + p] += a1;
            }
            __syncthreads();
        }

        for (int k = t; k < 4096; k += 128) {
            int ci = k >> 6, p = k & 63;
            tm[k] = ts[k]*d_m2[(b*64+ci)*64 + p];
        }
        __syncthreads();
        for (int k = t; k < 1024; k += 128) {
            int op = k >> 6, p = k & 63;
            int o0 = 2*op, o1 = o0 + 1;
            float a0 = 0.f, a1 = 0.f;
            #pragma unroll
            for (int cc = 0; cc < 16; cc++) {
                float4 w0 = __ldg((const float4*)(w2c + o0*64 + cc*4));
                float4 w1 = __ldg((const float4*)(w2c + o1*64 + cc*4));
                float t0 = tm[(cc*4+0)*64+p], t1 = tm[(cc*4+1)*64+p];
                float t2 = tm[(cc*4+2)*64+p], t3 = tm[(cc*4+3)*64+p];
                a0 += w0.x*t0 + w0.y*t1 + w0.z*t2 + w0.w*t3;
                a1 += w1.x*t0 + w1.y*t1 + w1.z*t2 + w1.w*t3;
            }
            d_V[((b*64+i)*32 + o0)*64 + p] = a0;
            d_V[((b*64+i)*32 + o1)*64 + p] = a1;
        }
    }
}

// ---- final: argmin + gather + scatter + hopfield(out). grid 64, 256 thr ----
__global__ void __launch_bounds__(256) final_kernel(const float* __restrict__ pats,
                                                    float* __restrict__ out)
{
    extern __shared__ float sm[];
    float* ps  = sm;            // 512*33 = 16896
    float* red = ps + 16896;    // 8448
    float* Us  = red + 8448;    // 2048
    float* ym  = Us + 2048;     // 2048
    int*   ix  = (int*)(ym + 2048);  // 64
    int t = threadIdx.x;
    int b = blockIdx.x >> 3, chunk = blockIdx.x & 7;

    load_ps(ps, pats, t, 256);
    if (t < 64) {
        float best = d_etot[(b*64+0)*64 + t]; int bi = 0;
        for (int s = 1; s < 64; s++) {
            float v = d_etot[(b*64+s)*64 + t];
            if (v < best) { best = v; bi = s; }
        }
        ix[t] = bi;
    }
    __syncthreads();
    for (int k = t; k < 2048; k += 256) {
        int i = k >> 5, o = k & 31;
        Us[k] = d_V[((b*64+i)*32 + o)*64 + ix[i]];
    }
    __syncthreads();
    for (int k = t; k < 2048; k += 256) {
        int o = k >> 6, m = k & 63;
        float acc = 0.f;
        for (int ii = 0; ii < 64; ii++)
            acc += (ix[ii] == m) ? Us[ii*32 + o] : 0.f;
        ym[o*64 + m] = acc;
    }
    __syncthreads();
    {
        int lane = t & 31, wid = t >> 5;
        int p = chunk*8 + wid;
        float yv[32];
        #pragma unroll
        for (int c = 0; c < 32; c++) yv[c] = ym[c*64 + p];
        float q = hop_core(ps, red, yv, lane, wid);
        out[b*2048 + lane*64 + p] = q;
    }
}

extern "C" void kernel_launch(void* const* d_in, const int* in_sizes, int n_in,
                              void* d_out, int out_size)
{
    const float* x    = (const float*)d_in[0];
    const float* w1c  = (const float*)d_in[1];
    const float* b1   = (const float*)d_in[2];
    const float* rw1a = (const float*)d_in[3];
    const float* rw2a = (const float*)d_in[4];
    const float* rw1b = (const float*)d_in[5];
    const float* rw2b = (const float*)d_in[6];
    const float* w2c  = (const float*)d_in[7];
    const float* b2   = (const float*)d_in[8];
    const float* pats = (const float*)d_in[9];
    float* out = (float*)d_out;

    const int SEED = 13888*4;                      // 55.5 KB -> 4 CTAs/SM
    const int FWD2 = (2048 + 16896 + 8448)*4;      // 109.6 KB
    const int FIN  = (16896 + 8448 + 2048 + 2048 + 64)*4;  // 118 KB
    cudaFuncSetAttribute(seed_kernel,  cudaFuncAttributeMaxDynamicSharedMemorySize, SEED);
    cudaFuncSetAttribute(fwd2_kernel,  cudaFuncAttributeMaxDynamicSharedMemorySize, FWD2);
    cudaFuncSetAttribute(final_kernel, cudaFuncAttributeMaxDynamicSharedMemorySize, FIN);

    prep_kernel<<<240, 256>>>(x, w1c, rw1a, rw1b);
    fwd2_kernel<<<64, 256, FWD2>>>(b1, rw2a, rw2b, w2c, b2, pats);
    seed_kernel<<<dim3(64,8,2), 128, SEED>>>(x, w1c, rw2a, rw2b, w2c);
    final_kernel<<<64, 256, FIN>>>(pats, out);
}